// round 4
// baseline (speedup 1.0000x reference)
#include <cuda_runtime.h>
#include <cuda_bf16.h>
#include <math.h>
#include <stdint.h>

// ---------------------------------------------------------------------------
// TransformerXL RPE via bf16x3 (emulated fp32) mma.sync GEMMs.
// out[b,i,j] = ( (Q+u)[b,i,:]·K[b,j,:] + A[b,i, clip(i-j)+M] ) / sqrt(D)
// Q = x@Wq^T, K = x@Wk^T, R = table@Wr^T, A = (Q+v)@R^T.
// Split a = hi + lo (bf16); a*b ~= ah*bh + ah*bl + al*bh, fp32 accumulate.
// CTA tile 128x256, warp tile 64x64, BK=64, 2-stage cp.async pipeline.
// ---------------------------------------------------------------------------

#define SDIV(a,b) (((a)+(b)-1)/(b))

static constexpr int A_TILE_B = 128 * 128;        // 128 rows x 64 bf16 = 16 KB
static constexpr int B_TILE_B = 256 * 128;        // 256 rows x 64 bf16 = 32 KB
static constexpr int STAGE_B  = 2 * A_TILE_B + 2 * B_TILE_B;   // 96 KB
static constexpr int SMEM_REQ = 2 * STAGE_B;      // 192 KB
static constexpr int LDP      = 1028;             // padded ld for A (pos) matrix

// ---------------- scratch (B=4, L=2048, D=1024, 2M+1=1025) -----------------
__device__ __align__(1024) __nv_bfloat16 g_xh [8192u*1024u];
__device__ __align__(1024) __nv_bfloat16 g_xl [8192u*1024u];
__device__ __align__(1024) __nv_bfloat16 g_wqh[1024u*1024u];
__device__ __align__(1024) __nv_bfloat16 g_wql[1024u*1024u];
__device__ __align__(1024) __nv_bfloat16 g_wkh[1024u*1024u];
__device__ __align__(1024) __nv_bfloat16 g_wkl[1024u*1024u];
__device__ __align__(1024) __nv_bfloat16 g_wrh[1024u*1024u];
__device__ __align__(1024) __nv_bfloat16 g_wrl[1024u*1024u];
__device__ __align__(1024) __nv_bfloat16 g_tbh[1025u*1024u];
__device__ __align__(1024) __nv_bfloat16 g_tbl[1025u*1024u];
__device__ __align__(1024) __nv_bfloat16 g_quh[8192u*1024u];
__device__ __align__(1024) __nv_bfloat16 g_qul[8192u*1024u];
__device__ __align__(1024) __nv_bfloat16 g_qvh[8192u*1024u];
__device__ __align__(1024) __nv_bfloat16 g_qvl[8192u*1024u];
__device__ __align__(1024) __nv_bfloat16 g_kh [8192u*1024u];
__device__ __align__(1024) __nv_bfloat16 g_kl [8192u*1024u];
__device__ __align__(1024) __nv_bfloat16 g_rh [1025u*1024u];
__device__ __align__(1024) __nv_bfloat16 g_rl [1025u*1024u];
__device__ __align__(1024) float         g_A  [8192u*(unsigned)LDP];

// ---------------------------- PTX helpers ----------------------------------
__device__ __forceinline__ uint32_t smem_u32(const void* p) {
    uint32_t a;
    asm("{ .reg .u64 t; cvta.to.shared.u64 t, %1; cvt.u32.u64 %0, t; }" : "=r"(a) : "l"(p));
    return a;
}
#define CP_ASYNC16(dst, src, pbytes) \
    asm volatile("cp.async.cg.shared.global [%0], [%1], 16, %2;" \
                 :: "r"(dst), "l"(src), "r"(pbytes))
#define CP_COMMIT() asm volatile("cp.async.commit_group;" ::: "memory")
#define CP_WAIT1()  asm volatile("cp.async.wait_group 1;"  ::: "memory")

#define LDSM_X4(r0,r1,r2,r3,a) \
    asm volatile("ldmatrix.sync.aligned.m8n8.x4.shared.b16 {%0,%1,%2,%3}, [%4];" \
                 : "=r"(r0), "=r"(r1), "=r"(r2), "=r"(r3) : "r"(a))
#define MMA16816(c, a, b0, b1) \
    asm volatile("mma.sync.aligned.m16n8k16.row.col.f32.bf16.bf16.f32 " \
                 "{%0,%1,%2,%3}, {%4,%5,%6,%7}, {%8,%9}, {%0,%1,%2,%3};" \
                 : "+f"((c)[0]), "+f"((c)[1]), "+f"((c)[2]), "+f"((c)[3]) \
                 : "r"((a)[0]), "r"((a)[1]), "r"((a)[2]), "r"((a)[3]), \
                   "r"(b0), "r"(b1))

__device__ __forceinline__ void split2(float a, __nv_bfloat16& h, __nv_bfloat16& l) {
    h = __float2bfloat16(a);
    l = __float2bfloat16(a - __bfloat162float(h));
}

// ------------------------- split input kernel -------------------------------
__global__ void split_kernel(const float* __restrict__ in,
                             __nv_bfloat16* __restrict__ hi,
                             __nv_bfloat16* __restrict__ lo, int n4) {
    int i = blockIdx.x * blockDim.x + threadIdx.x;
    if (i >= n4) return;
    float4 v = reinterpret_cast<const float4*>(in)[i];
    __nv_bfloat16 h0,l0,h1,l1,h2,l2,h3,l3;
    split2(v.x,h0,l0); split2(v.y,h1,l1); split2(v.z,h2,l2); split2(v.w,h3,l3);
    reinterpret_cast<__nv_bfloat162*>(hi)[i*2+0] = __halves2bfloat162(h0,h1);
    reinterpret_cast<__nv_bfloat162*>(hi)[i*2+1] = __halves2bfloat162(h2,h3);
    reinterpret_cast<__nv_bfloat162*>(lo)[i*2+0] = __halves2bfloat162(l0,l1);
    reinterpret_cast<__nv_bfloat162*>(lo)[i*2+1] = __halves2bfloat162(l2,l3);
}

// ---------------------- tile loader (cp.async, swizzled) --------------------
// Rows of 64 bf16 (128 B). Chunk c (16 B) of row r stored at
// r*128 + ((c ^ (r&7))*16)  -> conflict-free for cp.async and ldmatrix.
template <int ROWS>
__device__ __forceinline__ void load_tile(uint32_t dst, const __nv_bfloat16* g,
                                          int row0, int rows_max, int k0, int ld,
                                          int tid, bool bchk) {
#pragma unroll
    for (int i = 0; i < ROWS / 32; i++) {
        const int idx = tid + i * 256;
        const int r = idx >> 3, c = idx & 7;
        int row = row0 + r;
        unsigned p = 16;
        if (bchk && row >= rows_max) { p = 0; row = 0; }
        const __nv_bfloat16* src = g + (size_t)row * ld + k0 + c * 8;
        const uint32_t d = dst + r * 128 + (((c ^ (r & 7))) << 4);
        CP_ASYNC16(d, src, p);
    }
}

// ------------------------------ GEMM kernel ---------------------------------
// MODE 0: fp32 store (ldc)                                   [GEMM4 -> A]
// MODE 1: (acc+bias1)->C0/C1 hi/lo, (acc+bias2)->C2/C3 hi/lo [GEMM1]
// MODE 3: acc -> C0/C1 hi/lo                                 [GEMM2, GEMM3]
// MODE 2: (acc + Apos[m, clip(m-n)+mr]) * scale -> C0        [GEMM5, batched]
template <int MODE, bool BCHK>
__global__ __launch_bounds__(256, 1)
void tc_gemm(const __nv_bfloat16* __restrict__ gAh, const __nv_bfloat16* __restrict__ gAl,
             const __nv_bfloat16* __restrict__ gBh, const __nv_bfloat16* __restrict__ gBl,
             void* C0, void* C1, void* C2, void* C3,
             const float* __restrict__ bias1, const float* __restrict__ bias2,
             const float* __restrict__ Apos,
             int M, int N, int ld, int ldc, int rowOffA, int rowOffB,
             long long sC, long long sP, int maxrel, int ldp, float scale, int nk)
{
    extern __shared__ __align__(128) char smem_raw[];
    const uint32_t sb = smem_u32(smem_raw);
    const int tid = threadIdx.x, lane = tid & 31, wid = tid >> 5;
    const int bm = blockIdx.y * 128, bn = blockIdx.x * 256, bz = blockIdx.z;
    const int wm = wid >> 2, wn = wid & 3;            // warp grid 2 x 4
    const int rA = bz * rowOffA + bm;
    const int rB = bz * rowOffB + bn;

    float acc[4][8][4];
#pragma unroll
    for (int mi = 0; mi < 4; mi++)
#pragma unroll
        for (int ni = 0; ni < 8; ni++)
#pragma unroll
            for (int q = 0; q < 4; q++) acc[mi][ni][q] = 0.f;

    auto load_stage = [&](int s, int t) {
        const uint32_t base = sb + s * STAGE_B;
        const int k0 = t * 64;
        load_tile<128>(base,                          gAh, rA, M, k0, ld, tid, BCHK);
        load_tile<128>(base + A_TILE_B,               gAl, rA, M, k0, ld, tid, BCHK);
        load_tile<256>(base + 2 * A_TILE_B,           gBh, rB, N, k0, ld, tid, BCHK);
        load_tile<256>(base + 2 * A_TILE_B + B_TILE_B, gBl, rB, N, k0, ld, tid, BCHK);
    };

    load_stage(0, 0); CP_COMMIT();
    if (nk > 1) load_stage(1, 1);
    CP_COMMIT();

    // ldmatrix lane-invariant address parts
    const int a_row = wm * 64 + (lane & 15);          // + mi*16
    const int b_row = wn * 64 + (lane & 15);          // + pair*16
    const int cc_add = lane >> 4;                     // + ks*2

    for (int t = 0; t < nk; t++) {
        CP_WAIT1();
        __syncthreads();

        const uint32_t base = sb + (t & 1) * STAGE_B;
        const uint32_t sAh = base, sAl = base + A_TILE_B;
        const uint32_t sBh = base + 2 * A_TILE_B, sBl = sBh + B_TILE_B;

#pragma unroll
        for (int ks = 0; ks < 4; ks++) {
            uint32_t fBh[4][4], fBl[4][4];
#pragma unroll
            for (int pr = 0; pr < 4; pr++) {
                const int row = b_row + pr * 16;
                const int cc = ks * 2 + cc_add;
                const uint32_t off = row * 128 + (((cc ^ (row & 7))) << 4);
                LDSM_X4(fBh[pr][0], fBh[pr][1], fBh[pr][2], fBh[pr][3], sBh + off);
                LDSM_X4(fBl[pr][0], fBl[pr][1], fBl[pr][2], fBl[pr][3], sBl + off);
            }
#pragma unroll
            for (int mi = 0; mi < 4; mi++) {
                const int row = a_row + mi * 16;
                const int cc = ks * 2 + cc_add;
                const uint32_t off = row * 128 + (((cc ^ (row & 7))) << 4);
                uint32_t fAh[4], fAl[4];
                LDSM_X4(fAh[0], fAh[1], fAh[2], fAh[3], sAh + off);
                LDSM_X4(fAl[0], fAl[1], fAl[2], fAl[3], sAl + off);
#pragma unroll
                for (int ni = 0; ni < 8; ni++) {
                    const int pr = ni >> 1, s = ni & 1;
                    MMA16816(acc[mi][ni], fAh, fBh[pr][s], fBh[pr][s + 2]);
                    MMA16816(acc[mi][ni], fAh, fBl[pr][s], fBl[pr][s + 2]);
                    MMA16816(acc[mi][ni], fAl, fBh[pr][s], fBh[pr][s + 2]);
                }
            }
        }

        __syncthreads();
        if (t + 2 < nk) load_stage(t & 1, t + 2);
        CP_COMMIT();
    }

    // ------------------------------ epilogue --------------------------------
    const int lr = lane >> 2, lc = (lane & 3) * 2;

#pragma unroll
    for (int mi = 0; mi < 4; mi++) {
#pragma unroll
        for (int ni = 0; ni < 8; ni++) {
            const float* cc = acc[mi][ni];
            const int n = bn + wn * 64 + ni * 8 + lc;
#pragma unroll
            for (int h = 0; h < 2; h++) {
                const int m = bm + wm * 64 + mi * 16 + lr + h * 8;
                const float v0 = cc[h * 2 + 0], v1 = cc[h * 2 + 1];
                if (MODE == 0) {
                    if (BCHK && m >= M) continue;
                    float* Cf = (float*)C0;
                    if (!BCHK || n + 1 < N) {
                        *reinterpret_cast<float2*>(Cf + (size_t)m * ldc + n) = make_float2(v0, v1);
                    } else if (n < N) {
                        Cf[(size_t)m * ldc + n] = v0;
                    }
                } else if (MODE == 3) {
                    if (BCHK && m >= M) continue;
                    __nv_bfloat16* Ch = (__nv_bfloat16*)C0;
                    __nv_bfloat16* Cl = (__nv_bfloat16*)C1;
                    __nv_bfloat16 h0, l0, h1, l1;
                    split2(v0, h0, l0); split2(v1, h1, l1);
                    const size_t o = (size_t)m * ldc + n;
                    *reinterpret_cast<__nv_bfloat162*>(Ch + o) = __halves2bfloat162(h0, h1);
                    *reinterpret_cast<__nv_bfloat162*>(Cl + o) = __halves2bfloat162(l0, l1);
                } else if (MODE == 1) {
                    __nv_bfloat16* Uh = (__nv_bfloat16*)C0;
                    __nv_bfloat16* Ul = (__nv_bfloat16*)C1;
                    __nv_bfloat16* Vh = (__nv_bfloat16*)C2;
                    __nv_bfloat16* Vl = (__nv_bfloat16*)C3;
                    const size_t o = (size_t)m * ldc + n;
                    __nv_bfloat16 h0, l0, h1, l1;
                    split2(v0 + bias1[n], h0, l0); split2(v1 + bias1[n + 1], h1, l1);
                    *reinterpret_cast<__nv_bfloat162*>(Uh + o) = __halves2bfloat162(h0, h1);
                    *reinterpret_cast<__nv_bfloat162*>(Ul + o) = __halves2bfloat162(l0, l1);
                    split2(v0 + bias2[n], h0, l0); split2(v1 + bias2[n + 1], h1, l1);
                    *reinterpret_cast<__nv_bfloat162*>(Vh + o) = __halves2bfloat162(h0, h1);
                    *reinterpret_cast<__nv_bfloat162*>(Vl + o) = __halves2bfloat162(l0, l1);
                } else { // MODE 2
                    const float* Ap = Apos + (size_t)bz * sP + (size_t)m * ldp + maxrel;
                    float* Ob = (float*)C0 + (size_t)bz * sC + (size_t)m * ldc;
                    int r0 = m - n;
                    r0 = r0 > maxrel ? maxrel : (r0 < -maxrel ? -maxrel : r0);
                    int r1 = m - (n + 1);
                    r1 = r1 > maxrel ? maxrel : (r1 < -maxrel ? -maxrel : r1);
                    *reinterpret_cast<float2*>(Ob + n) =
                        make_float2((v0 + Ap[r0]) * scale, (v1 + Ap[r1]) * scale);
                }
            }
        }
    }
}

// ------------------------------- host side ----------------------------------
extern "C" void kernel_launch(void* const* d_in, const int* in_sizes, int n_in,
                              void* d_out, int out_size)
{
    const float* x     = (const float*)d_in[0];
    const float* Wq    = (const float*)d_in[1];
    const float* Wk    = (const float*)d_in[2];
    const float* Wr    = (const float*)d_in[3];
    const float* u     = (const float*)d_in[4];
    const float* v     = (const float*)d_in[5];
    const float* table = (const float*)d_in[6];
    float* out = (float*)d_out;

    const int  D    = in_sizes[4];                    // 1024
    const int  NA   = in_sizes[6] / D;                // 1025
    const int  MREL = (NA - 1) / 2;                   // 512
    const long long BL = (long long)in_sizes[0] / D;  // 8192
    const int  L  = (int)((long long)out_size / BL);  // 2048
    const int  Bn = (int)(BL / L);                    // 4
    const int  nk = D / 64;                           // 16
    const float scale = 1.f / sqrtf((float)D);

    void *xh,*xl,*wqh,*wql,*wkh,*wkl,*wrh,*wrl,*tbh,*tbl;
    void *quh,*qul,*qvh,*qvl,*kh,*kl,*rh,*rl,*Aa;
    cudaGetSymbolAddress(&xh,  g_xh);  cudaGetSymbolAddress(&xl,  g_xl);
    cudaGetSymbolAddress(&wqh, g_wqh); cudaGetSymbolAddress(&wql, g_wql);
    cudaGetSymbolAddress(&wkh, g_wkh); cudaGetSymbolAddress(&wkl, g_wkl);
    cudaGetSymbolAddress(&wrh, g_wrh); cudaGetSymbolAddress(&wrl, g_wrl);
    cudaGetSymbolAddress(&tbh, g_tbh); cudaGetSymbolAddress(&tbl, g_tbl);
    cudaGetSymbolAddress(&quh, g_quh); cudaGetSymbolAddress(&qul, g_qul);
    cudaGetSymbolAddress(&qvh, g_qvh); cudaGetSymbolAddress(&qvl, g_qvl);
    cudaGetSymbolAddress(&kh,  g_kh);  cudaGetSymbolAddress(&kl,  g_kl);
    cudaGetSymbolAddress(&rh,  g_rh);  cudaGetSymbolAddress(&rl,  g_rl);
    cudaGetSymbolAddress(&Aa,  g_A);

    static bool attr_done = false;
    if (!attr_done) {
        cudaFuncSetAttribute(tc_gemm<1,false>, cudaFuncAttributeMaxDynamicSharedMemorySize, SMEM_REQ);
        cudaFuncSetAttribute(tc_gemm<3,false>, cudaFuncAttributeMaxDynamicSharedMemorySize, SMEM_REQ);
        cudaFuncSetAttribute(tc_gemm<3,true >, cudaFuncAttributeMaxDynamicSharedMemorySize, SMEM_REQ);
        cudaFuncSetAttribute(tc_gemm<0,true >, cudaFuncAttributeMaxDynamicSharedMemorySize, SMEM_REQ);
        cudaFuncSetAttribute(tc_gemm<2,false>, cudaFuncAttributeMaxDynamicSharedMemorySize, SMEM_REQ);
        attr_done = true;
    }

    // ---- split inputs ----
    {
        const int T = 256;
        int n4;
        n4 = (int)(BL * D / 4); split_kernel<<<SDIV(n4,T), T>>>(x,     (__nv_bfloat16*)xh,  (__nv_bfloat16*)xl,  n4);
        n4 = D * D / 4;         split_kernel<<<SDIV(n4,T), T>>>(Wq,    (__nv_bfloat16*)wqh, (__nv_bfloat16*)wql, n4);
                                split_kernel<<<SDIV(n4,T), T>>>(Wk,    (__nv_bfloat16*)wkh, (__nv_bfloat16*)wkl, n4);
                                split_kernel<<<SDIV(n4,T), T>>>(Wr,    (__nv_bfloat16*)wrh, (__nv_bfloat16*)wrl, n4);
        n4 = NA * D / 4;        split_kernel<<<SDIV(n4,T), T>>>(table, (__nv_bfloat16*)tbh, (__nv_bfloat16*)tbl, n4);
    }

    const dim3 blk(256);

    // 1) Qu/Qv = x@Wq^T + u/v  -> bf16 hi/lo (MODE 1)
    tc_gemm<1,false><<<dim3(D/256, (int)(BL/128), 1), blk, SMEM_REQ>>>(
        (const __nv_bfloat16*)xh, (const __nv_bfloat16*)xl,
        (const __nv_bfloat16*)wqh, (const __nv_bfloat16*)wql,
        quh, qul, qvh, qvl, u, v, nullptr,
        (int)BL, D, D, D, 0, 0, 0, 0, 0, 0, 0.f, nk);

    // 2) K = x@Wk^T -> bf16 hi/lo (MODE 3)
    tc_gemm<3,false><<<dim3(D/256, (int)(BL/128), 1), blk, SMEM_REQ>>>(
        (const __nv_bfloat16*)xh, (const __nv_bfloat16*)xl,
        (const __nv_bfloat16*)wkh, (const __nv_bfloat16*)wkl,
        kh, kl, nullptr, nullptr, nullptr, nullptr, nullptr,
        (int)BL, D, D, D, 0, 0, 0, 0, 0, 0, 0.f, nk);

    // 3) R = table@Wr^T -> bf16 hi/lo (MODE 3, M bounds 1025)
    tc_gemm<3,true><<<dim3(D/256, SDIV(NA,128), 1), blk, SMEM_REQ>>>(
        (const __nv_bfloat16*)tbh, (const __nv_bfloat16*)tbl,
        (const __nv_bfloat16*)wrh, (const __nv_bfloat16*)wrl,
        rh, rl, nullptr, nullptr, nullptr, nullptr, nullptr,
        NA, D, D, D, 0, 0, 0, 0, 0, 0, 0.f, nk);

    // 4) A = Qv@R^T -> fp32, ldc=LDP (MODE 0, N bounds 1025)
    tc_gemm<0,true><<<dim3(SDIV(NA,256), (int)(BL/128), 1), blk, SMEM_REQ>>>(
        (const __nv_bfloat16*)qvh, (const __nv_bfloat16*)qvl,
        (const __nv_bfloat16*)rh, (const __nv_bfloat16*)rl,
        Aa, nullptr, nullptr, nullptr, nullptr, nullptr, nullptr,
        (int)BL, NA, D, LDP, 0, 0, 0, 0, 0, 0, 0.f, nk);

    // 5) out = (Qu@K^T + gather(A)) * scale, batched over B (MODE 2)
    tc_gemm<2,false><<<dim3(L/256, L/128, Bn), blk, SMEM_REQ>>>(
        (const __nv_bfloat16*)quh, (const __nv_bfloat16*)qul,
        (const __nv_bfloat16*)kh, (const __nv_bfloat16*)kl,
        out, nullptr, nullptr, nullptr, nullptr, nullptr, (const float*)Aa,
        L, L, D, L, L, L,
        (long long)L * L, (long long)L * LDP, MREL, LDP, scale, nk);
}

// round 5
// speedup vs baseline: 1.1164x; 1.1164x over previous
#include <cuda_runtime.h>
#include <cuda_bf16.h>
#include <math.h>
#include <stdint.h>

// ---------------------------------------------------------------------------
// TransformerXL RPE via bf16x3 (emulated fp32) mma.sync GEMMs (sm_100 baseline
// ISA: HMMA + ldmatrix + cp.async).
// out[b,i,j] = ( (Q+u)[b,i,:]·K[b,j,:] + A[b,i, clip(i-j)+M] ) / sqrt(D)
// Q = x@Wq^T, K = x@Wk^T, R = table@Wr^T, A = (Q+v)@R^T.
// Split a = hi + lo (bf16); a*b ~= ah*bh + ah*bl + al*bh, fp32 accumulate.
// CTA tile 128x128, warp tile 64x32, BK=64, 3-stage cp.async pipeline.
// B fragments loaded as paired 16-row ldmatrix.x4 (12 ldmatrix / 48 MMA / ks).
// ---------------------------------------------------------------------------

#define SDIV(a,b) (((a)+(b)-1)/(b))

static constexpr int STG      = 3;
static constexpr int TILE_B   = 128 * 128;        // 128 rows x 64 bf16 = 16 KB
static constexpr int STAGE_B  = 4 * TILE_B;       // Ah, Al, Bh, Bl
static constexpr int SMEM_REQ = STG * STAGE_B;    // 192 KB
static constexpr int LDP      = 1028;             // padded ld for A (pos) matrix

// ---------------- scratch (B=4, L=2048, D=1024, 2M+1=1025) -----------------
__device__ __align__(1024) __nv_bfloat16 g_xh [8192u*1024u];
__device__ __align__(1024) __nv_bfloat16 g_xl [8192u*1024u];
__device__ __align__(1024) __nv_bfloat16 g_wqh[1024u*1024u];
__device__ __align__(1024) __nv_bfloat16 g_wql[1024u*1024u];
__device__ __align__(1024) __nv_bfloat16 g_wkh[1024u*1024u];
__device__ __align__(1024) __nv_bfloat16 g_wkl[1024u*1024u];
__device__ __align__(1024) __nv_bfloat16 g_wrh[1024u*1024u];
__device__ __align__(1024) __nv_bfloat16 g_wrl[1024u*1024u];
__device__ __align__(1024) __nv_bfloat16 g_tbh[1025u*1024u];
__device__ __align__(1024) __nv_bfloat16 g_tbl[1025u*1024u];
__device__ __align__(1024) __nv_bfloat16 g_quh[8192u*1024u];
__device__ __align__(1024) __nv_bfloat16 g_qul[8192u*1024u];
__device__ __align__(1024) __nv_bfloat16 g_qvh[8192u*1024u];
__device__ __align__(1024) __nv_bfloat16 g_qvl[8192u*1024u];
__device__ __align__(1024) __nv_bfloat16 g_kh [8192u*1024u];
__device__ __align__(1024) __nv_bfloat16 g_kl [8192u*1024u];
__device__ __align__(1024) __nv_bfloat16 g_rh [1025u*1024u];
__device__ __align__(1024) __nv_bfloat16 g_rl [1025u*1024u];
__device__ __align__(1024) float         g_A  [8192u*(unsigned)LDP];

// ---------------------------- PTX helpers ----------------------------------
__device__ __forceinline__ uint32_t smem_u32(const void* p) {
    uint32_t a;
    asm("{ .reg .u64 t; cvta.to.shared.u64 t, %1; cvt.u32.u64 %0, t; }" : "=r"(a) : "l"(p));
    return a;
}
#define CP_ASYNC16(dst, src, pbytes) \
    asm volatile("cp.async.cg.shared.global [%0], [%1], 16, %2;" \
                 :: "r"(dst), "l"(src), "r"(pbytes))
#define CP_COMMIT() asm volatile("cp.async.commit_group;" ::: "memory")
#define CP_WAIT1()  asm volatile("cp.async.wait_group 1;"  ::: "memory")

#define LDSM_X4(r0,r1,r2,r3,a) \
    asm volatile("ldmatrix.sync.aligned.m8n8.x4.shared.b16 {%0,%1,%2,%3}, [%4];" \
                 : "=r"(r0), "=r"(r1), "=r"(r2), "=r"(r3) : "r"(a))
#define MMA16816(c, a, b0, b1) \
    asm volatile("mma.sync.aligned.m16n8k16.row.col.f32.bf16.bf16.f32 " \
                 "{%0,%1,%2,%3}, {%4,%5,%6,%7}, {%8,%9}, {%0,%1,%2,%3};" \
                 : "+f"((c)[0]), "+f"((c)[1]), "+f"((c)[2]), "+f"((c)[3]) \
                 : "r"((a)[0]), "r"((a)[1]), "r"((a)[2]), "r"((a)[3]), \
                   "r"(b0), "r"(b1))

__device__ __forceinline__ void split2(float a, __nv_bfloat16& h, __nv_bfloat16& l) {
    h = __float2bfloat16(a);
    l = __float2bfloat16(a - __bfloat162float(h));
}

// ------------------------- split input kernel -------------------------------
__global__ void split_kernel(const float* __restrict__ in,
                             __nv_bfloat16* __restrict__ hi,
                             __nv_bfloat16* __restrict__ lo, int n4) {
    int i = blockIdx.x * blockDim.x + threadIdx.x;
    if (i >= n4) return;
    float4 v = reinterpret_cast<const float4*>(in)[i];
    __nv_bfloat16 h0,l0,h1,l1,h2,l2,h3,l3;
    split2(v.x,h0,l0); split2(v.y,h1,l1); split2(v.z,h2,l2); split2(v.w,h3,l3);
    reinterpret_cast<__nv_bfloat162*>(hi)[i*2+0] = __halves2bfloat162(h0,h1);
    reinterpret_cast<__nv_bfloat162*>(hi)[i*2+1] = __halves2bfloat162(h2,h3);
    reinterpret_cast<__nv_bfloat162*>(lo)[i*2+0] = __halves2bfloat162(l0,l1);
    reinterpret_cast<__nv_bfloat162*>(lo)[i*2+1] = __halves2bfloat162(l2,l3);
}

// ---------------------- tile loader (cp.async, swizzled) --------------------
// Tile: 128 rows x 64 bf16 (128 B rows). Chunk c (16 B) of row r stored at
// r*128 + ((c ^ (r&7))*16)  -> conflict-free for both cp.async and ldmatrix.
__device__ __forceinline__ void load_tile(uint32_t dst, const __nv_bfloat16* g,
                                          int row0, int rows_max, int k0, int ld,
                                          int tid, bool bchk) {
#pragma unroll
    for (int i = 0; i < 4; i++) {
        const int idx = tid + i * 256;
        const int r = idx >> 3, c = idx & 7;
        int row = row0 + r;
        unsigned p = 16;
        if (bchk && row >= rows_max) { p = 0; row = 0; }
        const __nv_bfloat16* src = g + (size_t)row * ld + k0 + c * 8;
        const uint32_t d = dst + r * 128 + (((c ^ (r & 7))) << 4);
        CP_ASYNC16(d, src, p);
    }
}

// ------------------------------ GEMM kernel ---------------------------------
// MODE 0: fp32 store (ldc)                                   [GEMM4 -> A]
// MODE 1: (acc+bias1)->C0/C1 hi/lo, (acc+bias2)->C2/C3 hi/lo [GEMM1]
// MODE 3: acc -> C0/C1 hi/lo                                 [GEMM2, GEMM3]
// MODE 2: (acc + Apos[m, clip(m-n)+mr]) * scale -> C0        [GEMM5, batched]
template <int MODE, bool BCHK>
__global__ __launch_bounds__(256, 1)
void tc_gemm(const __nv_bfloat16* __restrict__ gAh, const __nv_bfloat16* __restrict__ gAl,
             const __nv_bfloat16* __restrict__ gBh, const __nv_bfloat16* __restrict__ gBl,
             void* C0, void* C1, void* C2, void* C3,
             const float* __restrict__ bias1, const float* __restrict__ bias2,
             const float* __restrict__ Apos,
             int M, int N, int ld, int ldc, int rowOffA, int rowOffB,
             long long sC, long long sP, int maxrel, int ldp, float scale, int nk)
{
    extern __shared__ __align__(128) char smem_raw[];
    const uint32_t sb = smem_u32(smem_raw);
    const int tid = threadIdx.x, lane = tid & 31, wid = tid >> 5;
    const int bm = blockIdx.y * 128, bn = blockIdx.x * 128, bz = blockIdx.z;
    const int wm = wid >> 2, wn = wid & 3;            // warp grid 2 x 4
    const int rA = bz * rowOffA + bm;
    const int rB = bz * rowOffB + bn;

    float acc[4][4][4];
#pragma unroll
    for (int mi = 0; mi < 4; mi++)
#pragma unroll
        for (int ni = 0; ni < 4; ni++)
#pragma unroll
            for (int q = 0; q < 4; q++) acc[mi][ni][q] = 0.f;

    auto load_stage = [&](int s, int t) {
        const uint32_t base = sb + s * STAGE_B;
        const int k0 = t * 64;
        load_tile(base + 0 * TILE_B, gAh, rA, M, k0, ld, tid, BCHK);
        load_tile(base + 1 * TILE_B, gAl, rA, M, k0, ld, tid, BCHK);
        load_tile(base + 2 * TILE_B, gBh, rB, N, k0, ld, tid, BCHK);
        load_tile(base + 3 * TILE_B, gBl, rB, N, k0, ld, tid, BCHK);
    };

    load_stage(0, 0); CP_COMMIT();
    load_stage(1, 1); CP_COMMIT();

    // ldmatrix lane-invariant address parts
    const int a_row = wm * 64 + (lane & 15);          // + mi*16
    const int b_row = wn * 32 + (lane & 15);          // + pr*16
    const int cc_add = lane >> 4;                     // + ks*2

    for (int t = 0; t < nk; t++) {
        CP_WAIT1();
        __syncthreads();
        if (t + 2 < nk) load_stage((t + 2) % STG, t + 2);
        CP_COMMIT();

        const uint32_t base = sb + (t % STG) * STAGE_B;
        const uint32_t sAh = base, sAl = base + TILE_B;
        const uint32_t sBh = base + 2 * TILE_B, sBl = base + 3 * TILE_B;

#pragma unroll
        for (int ks = 0; ks < 4; ks++) {
            const int cc = ks * 2 + cc_add;
            // B fragments: 2 paired 16-row x4 loads per tile (hi & lo)
            uint32_t fBh[2][4], fBl[2][4];
#pragma unroll
            for (int pr = 0; pr < 2; pr++) {
                const int row = b_row + pr * 16;
                const uint32_t off = row * 128 + (((cc ^ (row & 7))) << 4);
                LDSM_X4(fBh[pr][0], fBh[pr][1], fBh[pr][2], fBh[pr][3], sBh + off);
                LDSM_X4(fBl[pr][0], fBl[pr][1], fBl[pr][2], fBl[pr][3], sBl + off);
            }
#pragma unroll
            for (int mi = 0; mi < 4; mi++) {
                const int row = a_row + mi * 16;
                const uint32_t off = row * 128 + (((cc ^ (row & 7))) << 4);
                uint32_t fAh[4], fAl[4];
                LDSM_X4(fAh[0], fAh[1], fAh[2], fAh[3], sAh + off);
                LDSM_X4(fAl[0], fAl[1], fAl[2], fAl[3], sAl + off);
#pragma unroll
                for (int ni = 0; ni < 4; ni++) {
                    const int pr = ni >> 1, s = ni & 1;
                    MMA16816(acc[mi][ni], fAh, fBh[pr][s], fBh[pr][s + 2]);
                    MMA16816(acc[mi][ni], fAh, fBl[pr][s], fBl[pr][s + 2]);
                    MMA16816(acc[mi][ni], fAl, fBh[pr][s], fBh[pr][s + 2]);
                }
            }
        }
    }

    // ------------------------------ epilogue --------------------------------
    const int lr = lane >> 2, lc = (lane & 3) * 2;

#pragma unroll
    for (int mi = 0; mi < 4; mi++) {
#pragma unroll
        for (int ni = 0; ni < 4; ni++) {
            const float* cc = acc[mi][ni];
            const int n = bn + wn * 32 + ni * 8 + lc;
#pragma unroll
            for (int h = 0; h < 2; h++) {
                const int m = bm + wm * 64 + mi * 16 + lr + h * 8;
                const float v0 = cc[h * 2 + 0], v1 = cc[h * 2 + 1];
                if (MODE == 0) {
                    if (BCHK && m >= M) continue;
                    float* Cf = (float*)C0;
                    if (!BCHK || n + 1 < N) {
                        *reinterpret_cast<float2*>(Cf + (size_t)m * ldc + n) = make_float2(v0, v1);
                    } else if (n < N) {
                        Cf[(size_t)m * ldc + n] = v0;
                    }
                } else if (MODE == 3) {
                    if (BCHK && m >= M) continue;
                    __nv_bfloat16* Ch = (__nv_bfloat16*)C0;
                    __nv_bfloat16* Cl = (__nv_bfloat16*)C1;
                    __nv_bfloat16 h0, l0, h1, l1;
                    split2(v0, h0, l0); split2(v1, h1, l1);
                    const size_t o = (size_t)m * ldc + n;
                    *reinterpret_cast<__nv_bfloat162*>(Ch + o) = __halves2bfloat162(h0, h1);
                    *reinterpret_cast<__nv_bfloat162*>(Cl + o) = __halves2bfloat162(l0, l1);
                } else if (MODE == 1) {
                    __nv_bfloat16* Uh = (__nv_bfloat16*)C0;
                    __nv_bfloat16* Ul = (__nv_bfloat16*)C1;
                    __nv_bfloat16* Vh = (__nv_bfloat16*)C2;
                    __nv_bfloat16* Vl = (__nv_bfloat16*)C3;
                    const size_t o = (size_t)m * ldc + n;
                    __nv_bfloat16 h0, l0, h1, l1;
                    split2(v0 + bias1[n], h0, l0); split2(v1 + bias1[n + 1], h1, l1);
                    *reinterpret_cast<__nv_bfloat162*>(Uh + o) = __halves2bfloat162(h0, h1);
                    *reinterpret_cast<__nv_bfloat162*>(Ul + o) = __halves2bfloat162(l0, l1);
                    split2(v0 + bias2[n], h0, l0); split2(v1 + bias2[n + 1], h1, l1);
                    *reinterpret_cast<__nv_bfloat162*>(Vh + o) = __halves2bfloat162(h0, h1);
                    *reinterpret_cast<__nv_bfloat162*>(Vl + o) = __halves2bfloat162(l0, l1);
                } else { // MODE 2
                    const float* Ap = Apos + (size_t)bz * sP + (size_t)m * ldp + maxrel;
                    float* Ob = (float*)C0 + (size_t)bz * sC + (size_t)m * ldc;
                    int r0 = m - n;
                    r0 = r0 > maxrel ? maxrel : (r0 < -maxrel ? -maxrel : r0);
                    int r1 = m - (n + 1);
                    r1 = r1 > maxrel ? maxrel : (r1 < -maxrel ? -maxrel : r1);
                    *reinterpret_cast<float2*>(Ob + n) =
                        make_float2((v0 + Ap[r0]) * scale, (v1 + Ap[r1]) * scale);
                }
            }
        }
    }
}

// ------------------------------- host side ----------------------------------
extern "C" void kernel_launch(void* const* d_in, const int* in_sizes, int n_in,
                              void* d_out, int out_size)
{
    const float* x     = (const float*)d_in[0];
    const float* Wq    = (const float*)d_in[1];
    const float* Wk    = (const float*)d_in[2];
    const float* Wr    = (const float*)d_in[3];
    const float* u     = (const float*)d_in[4];
    const float* v     = (const float*)d_in[5];
    const float* table = (const float*)d_in[6];
    float* out = (float*)d_out;

    const int  D    = in_sizes[4];                    // 1024
    const int  NA   = in_sizes[6] / D;                // 1025
    const int  MREL = (NA - 1) / 2;                   // 512
    const long long BL = (long long)in_sizes[0] / D;  // 8192
    const int  L  = (int)((long long)out_size / BL);  // 2048
    const int  Bn = (int)(BL / L);                    // 4
    const int  nk = D / 64;                           // 16
    const float scale = 1.f / sqrtf((float)D);

    void *xh,*xl,*wqh,*wql,*wkh,*wkl,*wrh,*wrl,*tbh,*tbl;
    void *quh,*qul,*qvh,*qvl,*kh,*kl,*rh,*rl,*Aa;
    cudaGetSymbolAddress(&xh,  g_xh);  cudaGetSymbolAddress(&xl,  g_xl);
    cudaGetSymbolAddress(&wqh, g_wqh); cudaGetSymbolAddress(&wql, g_wql);
    cudaGetSymbolAddress(&wkh, g_wkh); cudaGetSymbolAddress(&wkl, g_wkl);
    cudaGetSymbolAddress(&wrh, g_wrh); cudaGetSymbolAddress(&wrl, g_wrl);
    cudaGetSymbolAddress(&tbh, g_tbh); cudaGetSymbolAddress(&tbl, g_tbl);
    cudaGetSymbolAddress(&quh, g_quh); cudaGetSymbolAddress(&qul, g_qul);
    cudaGetSymbolAddress(&qvh, g_qvh); cudaGetSymbolAddress(&qvl, g_qvl);
    cudaGetSymbolAddress(&kh,  g_kh);  cudaGetSymbolAddress(&kl,  g_kl);
    cudaGetSymbolAddress(&rh,  g_rh);  cudaGetSymbolAddress(&rl,  g_rl);
    cudaGetSymbolAddress(&Aa,  g_A);

    static bool attr_done = false;
    if (!attr_done) {
        cudaFuncSetAttribute(tc_gemm<1,false>, cudaFuncAttributeMaxDynamicSharedMemorySize, SMEM_REQ);
        cudaFuncSetAttribute(tc_gemm<3,false>, cudaFuncAttributeMaxDynamicSharedMemorySize, SMEM_REQ);
        cudaFuncSetAttribute(tc_gemm<3,true >, cudaFuncAttributeMaxDynamicSharedMemorySize, SMEM_REQ);
        cudaFuncSetAttribute(tc_gemm<0,true >, cudaFuncAttributeMaxDynamicSharedMemorySize, SMEM_REQ);
        cudaFuncSetAttribute(tc_gemm<2,false>, cudaFuncAttributeMaxDynamicSharedMemorySize, SMEM_REQ);
        attr_done = true;
    }

    // ---- split inputs ----
    {
        const int T = 256;
        int n4;
        n4 = (int)(BL * D / 4); split_kernel<<<SDIV(n4,T), T>>>(x,     (__nv_bfloat16*)xh,  (__nv_bfloat16*)xl,  n4);
        n4 = D * D / 4;         split_kernel<<<SDIV(n4,T), T>>>(Wq,    (__nv_bfloat16*)wqh, (__nv_bfloat16*)wql, n4);
                                split_kernel<<<SDIV(n4,T), T>>>(Wk,    (__nv_bfloat16*)wkh, (__nv_bfloat16*)wkl, n4);
                                split_kernel<<<SDIV(n4,T), T>>>(Wr,    (__nv_bfloat16*)wrh, (__nv_bfloat16*)wrl, n4);
        n4 = NA * D / 4;        split_kernel<<<SDIV(n4,T), T>>>(table, (__nv_bfloat16*)tbh, (__nv_bfloat16*)tbl, n4);
    }

    const dim3 blk(256);

    // 1) Qu/Qv = x@Wq^T + u/v  -> bf16 hi/lo (MODE 1)
    tc_gemm<1,false><<<dim3(D/128, (int)(BL/128), 1), blk, SMEM_REQ>>>(
        (const __nv_bfloat16*)xh, (const __nv_bfloat16*)xl,
        (const __nv_bfloat16*)wqh, (const __nv_bfloat16*)wql,
        quh, qul, qvh, qvl, u, v, nullptr,
        (int)BL, D, D, D, 0, 0, 0, 0, 0, 0, 0.f, nk);

    // 2) K = x@Wk^T -> bf16 hi/lo (MODE 3)
    tc_gemm<3,false><<<dim3(D/128, (int)(BL/128), 1), blk, SMEM_REQ>>>(
        (const __nv_bfloat16*)xh, (const __nv_bfloat16*)xl,
        (const __nv_bfloat16*)wkh, (const __nv_bfloat16*)wkl,
        kh, kl, nullptr, nullptr, nullptr, nullptr, nullptr,
        (int)BL, D, D, D, 0, 0, 0, 0, 0, 0, 0.f, nk);

    // 3) R = table@Wr^T -> bf16 hi/lo (MODE 3, M bounds 1025)
    tc_gemm<3,true><<<dim3(D/128, SDIV(NA,128), 1), blk, SMEM_REQ>>>(
        (const __nv_bfloat16*)tbh, (const __nv_bfloat16*)tbl,
        (const __nv_bfloat16*)wrh, (const __nv_bfloat16*)wrl,
        rh, rl, nullptr, nullptr, nullptr, nullptr, nullptr,
        NA, D, D, D, 0, 0, 0, 0, 0, 0, 0.f, nk);

    // 4) A = Qv@R^T -> fp32, ldc=LDP (MODE 0, N bounds 1025)
    tc_gemm<0,true><<<dim3(SDIV(NA,128), (int)(BL/128), 1), blk, SMEM_REQ>>>(
        (const __nv_bfloat16*)qvh, (const __nv_bfloat16*)qvl,
        (const __nv_bfloat16*)rh, (const __nv_bfloat16*)rl,
        Aa, nullptr, nullptr, nullptr, nullptr, nullptr, nullptr,
        (int)BL, NA, D, LDP, 0, 0, 0, 0, 0, 0, 0.f, nk);

    // 5) out = (Qu@K^T + gather(A)) * scale, batched over B (MODE 2)
    tc_gemm<2,false><<<dim3(L/128, L/128, Bn), blk, SMEM_REQ>>>(
        (const __nv_bfloat16*)quh, (const __nv_bfloat16*)qul,
        (const __nv_bfloat16*)kh, (const __nv_bfloat16*)kl,
        out, nullptr, nullptr, nullptr, nullptr, nullptr, (const float*)Aa,
        L, L, D, L, L, L,
        (long long)L * L, (long long)L * LDP, MREL, LDP, scale, nk);
}

// round 6
// speedup vs baseline: 1.3285x; 1.1900x over previous
#include <cuda_runtime.h>
#include <cuda_bf16.h>
#include <math.h>
#include <stdint.h>

// ---------------------------------------------------------------------------
// TransformerXL RPE via bf16x3 (emulated fp32) mma.sync GEMMs (sm_100 baseline
// ISA: HMMA + ldmatrix + cp.async).
// out[b,i,j] = ( (Q+u)[b,i,:]·K[b,j,:] + A[b,i, clip(i-j)+M] ) / sqrt(D)
// Q = x@Wq^T, K = x@Wk^T, R = table@Wr^T, A = (Q+v)@R^T.
// Split a = hi + lo (bf16); a*b ~= ah*bh + ah*bl + al*bh, fp32 accumulate.
// R3-proven config: CTA 128x128, warp 64x32, BK=64, 3-stage cp.async.
// All input splits fused into ONE launch (profiler lands on tc_gemm).
// ---------------------------------------------------------------------------

#define SDIV(a,b) (((a)+(b)-1)/(b))

static constexpr int STG      = 3;
static constexpr int TILE_B   = 128 * 128;        // 128 rows x 64 bf16 = 16 KB
static constexpr int STAGE_B  = 4 * TILE_B;       // Ah, Al, Bh, Bl
static constexpr int SMEM_REQ = STG * STAGE_B;    // 192 KB
static constexpr int LDP      = 1028;             // padded ld for A (pos) matrix

// ---------------- scratch (B=4, L=2048, D=1024, 2M+1=1025) -----------------
__device__ __align__(1024) __nv_bfloat16 g_xh [8192u*1024u];
__device__ __align__(1024) __nv_bfloat16 g_xl [8192u*1024u];
__device__ __align__(1024) __nv_bfloat16 g_wqh[1024u*1024u];
__device__ __align__(1024) __nv_bfloat16 g_wql[1024u*1024u];
__device__ __align__(1024) __nv_bfloat16 g_wkh[1024u*1024u];
__device__ __align__(1024) __nv_bfloat16 g_wkl[1024u*1024u];
__device__ __align__(1024) __nv_bfloat16 g_wrh[1024u*1024u];
__device__ __align__(1024) __nv_bfloat16 g_wrl[1024u*1024u];
__device__ __align__(1024) __nv_bfloat16 g_tbh[1025u*1024u];
__device__ __align__(1024) __nv_bfloat16 g_tbl[1025u*1024u];
__device__ __align__(1024) __nv_bfloat16 g_quh[8192u*1024u];
__device__ __align__(1024) __nv_bfloat16 g_qul[8192u*1024u];
__device__ __align__(1024) __nv_bfloat16 g_qvh[8192u*1024u];
__device__ __align__(1024) __nv_bfloat16 g_qvl[8192u*1024u];
__device__ __align__(1024) __nv_bfloat16 g_kh [8192u*1024u];
__device__ __align__(1024) __nv_bfloat16 g_kl [8192u*1024u];
__device__ __align__(1024) __nv_bfloat16 g_rh [1025u*1024u];
__device__ __align__(1024) __nv_bfloat16 g_rl [1025u*1024u];
__device__ __align__(1024) float         g_A  [8192u*(unsigned)LDP];

// ---------------------------- PTX helpers ----------------------------------
__device__ __forceinline__ uint32_t smem_u32(const void* p) {
    uint32_t a;
    asm("{ .reg .u64 t; cvta.to.shared.u64 t, %1; cvt.u32.u64 %0, t; }" : "=r"(a) : "l"(p));
    return a;
}
#define CP_ASYNC16(dst, src, pbytes) \
    asm volatile("cp.async.cg.shared.global [%0], [%1], 16, %2;" \
                 :: "r"(dst), "l"(src), "r"(pbytes))
#define CP_COMMIT() asm volatile("cp.async.commit_group;" ::: "memory")
#define CP_WAIT1()  asm volatile("cp.async.wait_group 1;"  ::: "memory")

#define LDSM_X4(r0,r1,r2,r3,a) \
    asm volatile("ldmatrix.sync.aligned.m8n8.x4.shared.b16 {%0,%1,%2,%3}, [%4];" \
                 : "=r"(r0), "=r"(r1), "=r"(r2), "=r"(r3) : "r"(a))
#define LDSM_X2(r0,r1,a) \
    asm volatile("ldmatrix.sync.aligned.m8n8.x2.shared.b16 {%0,%1}, [%2];" \
                 : "=r"(r0), "=r"(r1) : "r"(a))
#define MMA16816(c, a, b) \
    asm volatile("mma.sync.aligned.m16n8k16.row.col.f32.bf16.bf16.f32 " \
                 "{%0,%1,%2,%3}, {%4,%5,%6,%7}, {%8,%9}, {%0,%1,%2,%3};" \
                 : "+f"((c)[0]), "+f"((c)[1]), "+f"((c)[2]), "+f"((c)[3]) \
                 : "r"((a)[0]), "r"((a)[1]), "r"((a)[2]), "r"((a)[3]), \
                   "r"((b)[0]), "r"((b)[1]))

__device__ __forceinline__ void split2(float a, __nv_bfloat16& h, __nv_bfloat16& l) {
    h = __float2bfloat16(a);
    l = __float2bfloat16(a - __bfloat162float(h));
}

// ------------------- fused split kernel (one launch, 5 segments) ------------
// Segment block-count prefixes are passed in; every segment's element count is
// an exact multiple of 256 float4s, so no bounds checks are needed.
__global__ void split5(const float* __restrict__ i0, const float* __restrict__ i1,
                       const float* __restrict__ i2, const float* __restrict__ i3,
                       const float* __restrict__ i4,
                       __nv_bfloat16* __restrict__ h0, __nv_bfloat16* __restrict__ l0,
                       __nv_bfloat16* __restrict__ h1, __nv_bfloat16* __restrict__ l1,
                       __nv_bfloat16* __restrict__ h2, __nv_bfloat16* __restrict__ l2,
                       __nv_bfloat16* __restrict__ h3, __nv_bfloat16* __restrict__ l3,
                       __nv_bfloat16* __restrict__ h4, __nv_bfloat16* __restrict__ l4,
                       int p0, int p1, int p2, int p3)
{
    int b = blockIdx.x;
    const float* in; __nv_bfloat16 *hi, *lo;
    if      (b < p0) { in = i0; hi = h0; lo = l0; }
    else if (b < p1) { in = i1; hi = h1; lo = l1; b -= p0; }
    else if (b < p2) { in = i2; hi = h2; lo = l2; b -= p1; }
    else if (b < p3) { in = i3; hi = h3; lo = l3; b -= p2; }
    else             { in = i4; hi = h4; lo = l4; b -= p3; }

    const int i = b * blockDim.x + threadIdx.x;
    float4 v = reinterpret_cast<const float4*>(in)[i];
    __nv_bfloat16 a0,b0,a1,b1,a2,b2,a3,b3;
    split2(v.x,a0,b0); split2(v.y,a1,b1); split2(v.z,a2,b2); split2(v.w,a3,b3);
    reinterpret_cast<__nv_bfloat162*>(hi)[i*2+0] = __halves2bfloat162(a0,a1);
    reinterpret_cast<__nv_bfloat162*>(hi)[i*2+1] = __halves2bfloat162(a2,a3);
    reinterpret_cast<__nv_bfloat162*>(lo)[i*2+0] = __halves2bfloat162(b0,b1);
    reinterpret_cast<__nv_bfloat162*>(lo)[i*2+1] = __halves2bfloat162(b2,b3);
}

// ---------------------- tile loader (cp.async, swizzled) --------------------
// Tile: 128 rows x 64 bf16 (128 B rows). Chunk c (16 B) of row r is stored at
// r*128 + ((c ^ (r&7))*16)  -> conflict-free for both cp.async and ldmatrix.
__device__ __forceinline__ void load_tile(uint32_t dst, const __nv_bfloat16* g,
                                          int row0, int rows_max, int k0, int ld,
                                          int tid, bool bchk) {
#pragma unroll
    for (int i = 0; i < 4; i++) {
        const int idx = tid + i * 256;
        const int r = idx >> 3, c = idx & 7;
        int row = row0 + r;
        unsigned p = 16;
        if (bchk && row >= rows_max) { p = 0; row = 0; }
        const __nv_bfloat16* src = g + (size_t)row * ld + k0 + c * 8;
        const uint32_t d = dst + r * 128 + (((c ^ (r & 7))) << 4);
        CP_ASYNC16(d, src, p);
    }
}

// ------------------------------ GEMM kernel ---------------------------------
// MODE 0: fp32 store (ldc)                                   [GEMM4 -> A]
// MODE 1: (acc+bias1)->C0/C1 hi/lo, (acc+bias2)->C2/C3 hi/lo [GEMM1]
// MODE 3: acc -> C0/C1 hi/lo                                 [GEMM2, GEMM3]
// MODE 2: (acc + Apos[m, clip(m-n)+mr]) * scale -> C0        [GEMM5, batched]
template <int MODE, bool BCHK>
__global__ __launch_bounds__(256, 1)
void tc_gemm(const __nv_bfloat16* __restrict__ gAh, const __nv_bfloat16* __restrict__ gAl,
             const __nv_bfloat16* __restrict__ gBh, const __nv_bfloat16* __restrict__ gBl,
             void* C0, void* C1, void* C2, void* C3,
             const float* __restrict__ bias1, const float* __restrict__ bias2,
             const float* __restrict__ Apos,
             int M, int N, int ld, int ldc, int rowOffA, int rowOffB,
             long long sC, long long sP, int maxrel, int ldp, float scale, int nk)
{
    extern __shared__ __align__(128) char smem_raw[];
    const uint32_t sb = smem_u32(smem_raw);
    const int tid = threadIdx.x, lane = tid & 31, wid = tid >> 5;
    const int bm = blockIdx.y * 128, bn = blockIdx.x * 128, bz = blockIdx.z;
    const int wm = wid >> 2, wn = wid & 3;            // warp grid 2 x 4
    const int rA = bz * rowOffA + bm;
    const int rB = bz * rowOffB + bn;

    float acc[4][4][4];
#pragma unroll
    for (int mi = 0; mi < 4; mi++)
#pragma unroll
        for (int ni = 0; ni < 4; ni++)
#pragma unroll
            for (int q = 0; q < 4; q++) acc[mi][ni][q] = 0.f;

    auto load_stage = [&](int s, int t) {
        const uint32_t base = sb + s * STAGE_B;
        const int k0 = t * 64;
        load_tile(base + 0 * TILE_B, gAh, rA, M, k0, ld, tid, BCHK);
        load_tile(base + 1 * TILE_B, gAl, rA, M, k0, ld, tid, BCHK);
        load_tile(base + 2 * TILE_B, gBh, rB, N, k0, ld, tid, BCHK);
        load_tile(base + 3 * TILE_B, gBl, rB, N, k0, ld, tid, BCHK);
    };

    load_stage(0, 0); CP_COMMIT();
    load_stage(1, 1); CP_COMMIT();

    // ldmatrix source addresses (lane-invariant parts)
    const int a_row = wm * 64 + (lane & 15);          // + mi*16
    const int a_cc  = lane >> 4;                      // + ks*2
    const int b_row = wn * 32 + (lane & 7);           // + ni*8
    const int b_cc  = (lane >> 3) & 1;                // + ks*2

    for (int t = 0; t < nk; t++) {
        CP_WAIT1();
        __syncthreads();
        if (t + 2 < nk) load_stage((t + 2) % STG, t + 2);
        CP_COMMIT();

        const uint32_t base = sb + (t % STG) * STAGE_B;
        const uint32_t sAh = base, sAl = base + TILE_B;
        const uint32_t sBh = base + 2 * TILE_B, sBl = base + 3 * TILE_B;

#pragma unroll
        for (int ks = 0; ks < 4; ks++) {
            uint32_t fAh[4][4], fAl[4][4], fBh[4][2], fBl[4][2];
#pragma unroll
            for (int mi = 0; mi < 4; mi++) {
                const int row = a_row + mi * 16;
                const int cc = ks * 2 + a_cc;
                const uint32_t off = row * 128 + (((cc ^ (row & 7))) << 4);
                LDSM_X4(fAh[mi][0], fAh[mi][1], fAh[mi][2], fAh[mi][3], sAh + off);
                LDSM_X4(fAl[mi][0], fAl[mi][1], fAl[mi][2], fAl[mi][3], sAl + off);
            }
#pragma unroll
            for (int ni = 0; ni < 4; ni++) {
                const int row = b_row + ni * 8;
                const int cc = ks * 2 + b_cc;
                const uint32_t off = row * 128 + (((cc ^ (row & 7))) << 4);
                LDSM_X2(fBh[ni][0], fBh[ni][1], sBh + off);
                LDSM_X2(fBl[ni][0], fBl[ni][1], sBl + off);
            }
#pragma unroll
            for (int mi = 0; mi < 4; mi++)
#pragma unroll
                for (int ni = 0; ni < 4; ni++) MMA16816(acc[mi][ni], fAh[mi], fBh[ni]);
#pragma unroll
            for (int mi = 0; mi < 4; mi++)
#pragma unroll
                for (int ni = 0; ni < 4; ni++) MMA16816(acc[mi][ni], fAh[mi], fBl[ni]);
#pragma unroll
            for (int mi = 0; mi < 4; mi++)
#pragma unroll
                for (int ni = 0; ni < 4; ni++) MMA16816(acc[mi][ni], fAl[mi], fBh[ni]);
        }
    }

    // ------------------------------ epilogue --------------------------------
    const int lr = lane >> 2, lc = (lane & 3) * 2;

#pragma unroll
    for (int mi = 0; mi < 4; mi++) {
#pragma unroll
        for (int ni = 0; ni < 4; ni++) {
            const float* cc = acc[mi][ni];
            const int n = bn + wn * 32 + ni * 8 + lc;
#pragma unroll
            for (int h = 0; h < 2; h++) {
                const int m = bm + wm * 64 + mi * 16 + lr + h * 8;
                const float v0 = cc[h * 2 + 0], v1 = cc[h * 2 + 1];
                if (MODE == 0) {
                    if (BCHK && m >= M) continue;
                    float* Cf = (float*)C0;
                    if (!BCHK || n + 1 < N) {
                        *reinterpret_cast<float2*>(Cf + (size_t)m * ldc + n) = make_float2(v0, v1);
                    } else if (n < N) {
                        Cf[(size_t)m * ldc + n] = v0;
                    }
                } else if (MODE == 3) {
                    if (BCHK && m >= M) continue;
                    __nv_bfloat16* Ch = (__nv_bfloat16*)C0;
                    __nv_bfloat16* Cl = (__nv_bfloat16*)C1;
                    __nv_bfloat16 h0, l0, h1, l1;
                    split2(v0, h0, l0); split2(v1, h1, l1);
                    const size_t o = (size_t)m * ldc + n;
                    *reinterpret_cast<__nv_bfloat162*>(Ch + o) = __halves2bfloat162(h0, h1);
                    *reinterpret_cast<__nv_bfloat162*>(Cl + o) = __halves2bfloat162(l0, l1);
                } else if (MODE == 1) {
                    __nv_bfloat16* Uh = (__nv_bfloat16*)C0;
                    __nv_bfloat16* Ul = (__nv_bfloat16*)C1;
                    __nv_bfloat16* Vh = (__nv_bfloat16*)C2;
                    __nv_bfloat16* Vl = (__nv_bfloat16*)C3;
                    const size_t o = (size_t)m * ldc + n;
                    __nv_bfloat16 h0, l0, h1, l1;
                    split2(v0 + bias1[n], h0, l0); split2(v1 + bias1[n + 1], h1, l1);
                    *reinterpret_cast<__nv_bfloat162*>(Uh + o) = __halves2bfloat162(h0, h1);
                    *reinterpret_cast<__nv_bfloat162*>(Ul + o) = __halves2bfloat162(l0, l1);
                    split2(v0 + bias2[n], h0, l0); split2(v1 + bias2[n + 1], h1, l1);
                    *reinterpret_cast<__nv_bfloat162*>(Vh + o) = __halves2bfloat162(h0, h1);
                    *reinterpret_cast<__nv_bfloat162*>(Vl + o) = __halves2bfloat162(l0, l1);
                } else { // MODE 2
                    const float* Ap = Apos + (size_t)bz * sP + (size_t)m * ldp + maxrel;
                    float* Ob = (float*)C0 + (size_t)bz * sC + (size_t)m * ldc;
                    int r0 = m - n;
                    r0 = r0 > maxrel ? maxrel : (r0 < -maxrel ? -maxrel : r0);
                    int r1 = m - (n + 1);
                    r1 = r1 > maxrel ? maxrel : (r1 < -maxrel ? -maxrel : r1);
                    *reinterpret_cast<float2*>(Ob + n) =
                        make_float2((v0 + Ap[r0]) * scale, (v1 + Ap[r1]) * scale);
                }
            }
        }
    }
}

// ------------------------------- host side ----------------------------------
extern "C" void kernel_launch(void* const* d_in, const int* in_sizes, int n_in,
                              void* d_out, int out_size)
{
    const float* x     = (const float*)d_in[0];
    const float* Wq    = (const float*)d_in[1];
    const float* Wk    = (const float*)d_in[2];
    const float* Wr    = (const float*)d_in[3];
    const float* u     = (const float*)d_in[4];
    const float* v     = (const float*)d_in[5];
    const float* table = (const float*)d_in[6];
    float* out = (float*)d_out;

    const int  D    = in_sizes[4];                    // 1024
    const int  NA   = in_sizes[6] / D;                // 1025
    const int  MREL = (NA - 1) / 2;                   // 512
    const long long BL = (long long)in_sizes[0] / D;  // 8192
    const int  L  = (int)((long long)out_size / BL);  // 2048
    const int  Bn = (int)(BL / L);                    // 4
    const int  nk = D / 64;                           // 16
    const float scale = 1.f / sqrtf((float)D);

    void *xh,*xl,*wqh,*wql,*wkh,*wkl,*wrh,*wrl,*tbh,*tbl;
    void *quh,*qul,*qvh,*qvl,*kh,*kl,*rh,*rl,*Aa;
    cudaGetSymbolAddress(&xh,  g_xh);  cudaGetSymbolAddress(&xl,  g_xl);
    cudaGetSymbolAddress(&wqh, g_wqh); cudaGetSymbolAddress(&wql, g_wql);
    cudaGetSymbolAddress(&wkh, g_wkh); cudaGetSymbolAddress(&wkl, g_wkl);
    cudaGetSymbolAddress(&wrh, g_wrh); cudaGetSymbolAddress(&wrl, g_wrl);
    cudaGetSymbolAddress(&tbh, g_tbh); cudaGetSymbolAddress(&tbl, g_tbl);
    cudaGetSymbolAddress(&quh, g_quh); cudaGetSymbolAddress(&qul, g_qul);
    cudaGetSymbolAddress(&qvh, g_qvh); cudaGetSymbolAddress(&qvl, g_qvl);
    cudaGetSymbolAddress(&kh,  g_kh);  cudaGetSymbolAddress(&kl,  g_kl);
    cudaGetSymbolAddress(&rh,  g_rh);  cudaGetSymbolAddress(&rl,  g_rl);
    cudaGetSymbolAddress(&Aa,  g_A);

    static bool attr_done = false;
    if (!attr_done) {
        cudaFuncSetAttribute(tc_gemm<1,false>, cudaFuncAttributeMaxDynamicSharedMemorySize, SMEM_REQ);
        cudaFuncSetAttribute(tc_gemm<3,false>, cudaFuncAttributeMaxDynamicSharedMemorySize, SMEM_REQ);
        cudaFuncSetAttribute(tc_gemm<3,true >, cudaFuncAttributeMaxDynamicSharedMemorySize, SMEM_REQ);
        cudaFuncSetAttribute(tc_gemm<0,true >, cudaFuncAttributeMaxDynamicSharedMemorySize, SMEM_REQ);
        cudaFuncSetAttribute(tc_gemm<2,false>, cudaFuncAttributeMaxDynamicSharedMemorySize, SMEM_REQ);
        attr_done = true;
    }

    // ---- fused split: one launch for x, Wq, Wk, Wr, table ----
    {
        const int T = 256;
        const int bx = (int)(BL * D / 4) / T;   // 8192
        const int bw = (D * D / 4) / T;         // 1024
        const int bt = (NA * D / 4) / T;        // 1025
        const int p0 = bx, p1 = p0 + bw, p2 = p1 + bw, p3 = p2 + bw;
        split5<<<p3 + bt, T>>>(x, Wq, Wk, Wr, table,
            (__nv_bfloat16*)xh,  (__nv_bfloat16*)xl,
            (__nv_bfloat16*)wqh, (__nv_bfloat16*)wql,
            (__nv_bfloat16*)wkh, (__nv_bfloat16*)wkl,
            (__nv_bfloat16*)wrh, (__nv_bfloat16*)wrl,
            (__nv_bfloat16*)tbh, (__nv_bfloat16*)tbl,
            p0, p1, p2, p3);
    }

    const dim3 blk(256);

    // 1) Qu/Qv = x@Wq^T + u/v  -> bf16 hi/lo (MODE 1)
    tc_gemm<1,false><<<dim3(D/128, (int)(BL/128), 1), blk, SMEM_REQ>>>(
        (const __nv_bfloat16*)xh, (const __nv_bfloat16*)xl,
        (const __nv_bfloat16*)wqh, (const __nv_bfloat16*)wql,
        quh, qul, qvh, qvl, u, v, nullptr,
        (int)BL, D, D, D, 0, 0, 0, 0, 0, 0, 0.f, nk);

    // 2) K = x@Wk^T -> bf16 hi/lo (MODE 3)
    tc_gemm<3,false><<<dim3(D/128, (int)(BL/128), 1), blk, SMEM_REQ>>>(
        (const __nv_bfloat16*)xh, (const __nv_bfloat16*)xl,
        (const __nv_bfloat16*)wkh, (const __nv_bfloat16*)wkl,
        kh, kl, nullptr, nullptr, nullptr, nullptr, nullptr,
        (int)BL, D, D, D, 0, 0, 0, 0, 0, 0, 0.f, nk);

    // 3) R = table@Wr^T -> bf16 hi/lo (MODE 3, M bounds 1025)
    tc_gemm<3,true><<<dim3(D/128, SDIV(NA,128), 1), blk, SMEM_REQ>>>(
        (const __nv_bfloat16*)tbh, (const __nv_bfloat16*)tbl,
        (const __nv_bfloat16*)wrh, (const __nv_bfloat16*)wrl,
        rh, rl, nullptr, nullptr, nullptr, nullptr, nullptr,
        NA, D, D, D, 0, 0, 0, 0, 0, 0, 0.f, nk);

    // 4) A = Qv@R^T -> fp32, ldc=LDP (MODE 0, N bounds 1025)
    tc_gemm<0,true><<<dim3(SDIV(NA,128), (int)(BL/128), 1), blk, SMEM_REQ>>>(
        (const __nv_bfloat16*)qvh, (const __nv_bfloat16*)qvl,
        (const __nv_bfloat16*)rh, (const __nv_bfloat16*)rl,
        Aa, nullptr, nullptr, nullptr, nullptr, nullptr, nullptr,
        (int)BL, NA, D, LDP, 0, 0, 0, 0, 0, 0, 0.f, nk);

    // 5) out = (Qu@K^T + gather(A)) * scale, batched over B (MODE 2)
    tc_gemm<2,false><<<dim3(L/128, L/128, Bn), blk, SMEM_REQ>>>(
        (const __nv_bfloat16*)quh, (const __nv_bfloat16*)qul,
        (const __nv_bfloat16*)kh, (const __nv_bfloat16*)kl,
        out, nullptr, nullptr, nullptr, nullptr, nullptr, (const float*)Aa,
        L, L, D, L, L, L,
        (long long)L * L, (long long)L * LDP, MREL, LDP, scale, nk);
}